// round 1
// baseline (speedup 1.0000x reference)
#include <cuda_runtime.h>

// Problem constants (x: [4,512,256,32] f32, weight: [256,256,32] f32)
#define NTOK   2048            // batch*seq
#define IFEAT  256
#define OFEAT  256
#define XROW   (IFEAT * 32)    // 8192 floats per token / per output row

// GEMM tiling: C_k tile = BN x BO per block, contraction chunk = 32 (one i)
#define BN 128
#define BO 64

// Raw (pre-normalization) results, [k][n][o] for coalesced GEMM stores.
__device__ float g_scratch[32u * NTOK * OFEAT];

// sign of e_a * e_b in Cl(4,1): reorder swaps + metric of annihilated gens (bit4 = -1)
__device__ __forceinline__ float gp_sign(int a, int b) {
    int s = 0, aa = a >> 1;
    while (aa) { s += __popc(aa & b); aa >>= 1; }
    float sg = (s & 1) ? -1.0f : 1.0f;
    if ((a & b) & 16) sg = -sg;
    return sg;
}

// out_raw[k][n][o] = sum_{i,j} x[n,i,j^k] * sign(j, j^k) * w[o,i,j]
__global__ __launch_bounds__(256)
void versor_gemm(const float* __restrict__ x, const float* __restrict__ w) {
    __shared__ float As[32][BN + 4];   // [j][n_local], +4 pad keeps 16B align for float4 reads
    __shared__ float Bs[32][BO + 4];   // [j][o_local]
    __shared__ float sgn_sh[32];

    const int k  = blockIdx.y;
    const int o0 = blockIdx.x * BO;
    const int n0 = blockIdx.z * BN;

    const int tx  = threadIdx.x;            // 0..15 -> o
    const int ty  = threadIdx.y;            // 0..15 -> n
    const int tid = ty * 16 + tx;

    if (tid < 32) sgn_sh[tid] = gp_sign(tid, tid ^ k);
    __syncthreads();

    const int j  = tid & 31;                 // loader lane's blade index
    const int r0 = tid >> 5;                 // 0..7
    const int jk = j ^ k;
    const float sj = sgn_sh[j];

    float acc[8][4];
    #pragma unroll
    for (int p = 0; p < 8; p++)
        #pragma unroll
        for (int q = 0; q < 4; q++) acc[p][q] = 0.0f;

    const float* xbase = x + (size_t)n0 * XROW + jk;  // + nl*XROW + i*32
    const float* wbase = w + (size_t)o0 * XROW + j;   // + ol*XROW + i*32

    for (int i = 0; i < IFEAT; i++) {
        // Load A tile: As[j][nl] = x[n0+nl, i, j^k] * sign(j, j^k)
        // warp lanes sweep j=0..31 at fixed nl -> 128B coalesced gmem reads (XOR is
        // a permutation inside the 128B group). Pad 4 -> 4-way STS conflict (cheap).
        const float* xi = xbase + (size_t)i * 32;
        #pragma unroll
        for (int rr = 0; rr < 16; rr++) {
            int nl = r0 + rr * 8;
            As[j][nl] = xi[(size_t)nl * XROW] * sj;
        }
        // Load B tile: Bs[j][ol] = w[o0+ol, i, j]
        const float* wi = wbase + (size_t)i * 32;
        #pragma unroll
        for (int rr = 0; rr < 8; rr++) {
            int ol = r0 + rr * 8;
            Bs[j][ol] = wi[(size_t)ol * XROW];
        }
        __syncthreads();

        #pragma unroll 8
        for (int kk = 0; kk < 32; kk++) {
            float4 a01 = *(const float4*)&As[kk][ty * 8];
            float4 a23 = *(const float4*)&As[kk][ty * 8 + 4];
            float4 b   = *(const float4*)&Bs[kk][tx * 4];
            float ra[8] = {a01.x, a01.y, a01.z, a01.w, a23.x, a23.y, a23.z, a23.w};
            float rb[4] = {b.x, b.y, b.z, b.w};
            #pragma unroll
            for (int p = 0; p < 8; p++)
                #pragma unroll
                for (int q = 0; q < 4; q++)
                    acc[p][q] += ra[p] * rb[q];
        }
        __syncthreads();
    }

    float* dst = g_scratch + ((size_t)k * NTOK + n0) * OFEAT + o0;
    #pragma unroll
    for (int p = 0; p < 8; p++) {
        float4 v = make_float4(acc[p][0], acc[p][1], acc[p][2], acc[p][3]);
        *(float4*)(dst + (size_t)(ty * 8 + p) * OFEAT + tx * 4) = v;
    }
}

// Gather all 32 blades of one (n,o), normalize, write [n][o][k] layout.
__global__ __launch_bounds__(256)
void versor_normalize(float* __restrict__ out) {
    int id = blockIdx.x * 256 + threadIdx.x;      // 0 .. NTOK*OFEAT-1
    int n = id >> 8;                              // OFEAT = 256
    int o = id & 255;

    float v[32];
    float ss = 0.0f;
    #pragma unroll
    for (int k = 0; k < 32; k++) {
        float t = g_scratch[((size_t)k * NTOK + n) * OFEAT + o];  // warp: 128B coalesced
        v[k] = t;
        ss += t * t;
    }
    float inv = rsqrtf(ss + 1e-6f);

    float4* dst = (float4*)(out + (size_t)id * 32);
    #pragma unroll
    for (int q = 0; q < 8; q++)
        dst[q] = make_float4(v[4*q] * inv, v[4*q+1] * inv, v[4*q+2] * inv, v[4*q+3] * inv);
}

extern "C" void kernel_launch(void* const* d_in, const int* in_sizes, int n_in,
                              void* d_out, int out_size) {
    const float* x = (const float*)d_in[0];   // [2048, 256, 32]
    const float* w = (const float*)d_in[1];   // [256, 256, 32]
    float* out = (float*)d_out;               // [2048, 256, 32]

    // grid: x = o-tiles (fastest) , y = blade k, z = n-tiles (slowest)
    // -> all 128 (o,k) blocks of one n-tile run adjacently: x n-tile stays in L2.
    dim3 grid(OFEAT / BO, 32, NTOK / BN);
    dim3 block(16, 16);
    versor_gemm<<<grid, block>>>(x, w);

    versor_normalize<<<(NTOK * OFEAT) / 256, 256>>>(out);
}

// round 3
// speedup vs baseline: 4.1195x; 4.1195x over previous
#include <cuda_runtime.h>
#include <cstdint>

#define NTOK 2048
#define XK   8192            // contraction = 256 ifeat * 32 blades
#define NOUT 8192            // 256 ofeat * 32 blades (final [n][o][k] layout)
#define BM 128
#define BN 128
#define BK 32
#define STAGES 3
#define NIT (XK / BK)        // 256
#define STAGE_BYTES 32768    // A 16KB + B 16KB
#define SMEM_TOTAL (STAGES * STAGE_BYTES)   // 98304

// ---- scratch (static __device__: no allocation) ----
__device__ float g_xr[(size_t)NTOK * XK];   // 64 MB  tf32-rounded x
__device__ float g_Bp[(size_t)NOUT * XK];   // 256 MB expanded+signed+rounded weight

// ---------------- helpers ----------------
__device__ __forceinline__ uint32_t smem_u32(const void* p) {
    uint32_t a;
    asm("{ .reg .u64 t; cvta.to.shared.u64 t, %1; cvt.u32.u64 %0, t; }" : "=r"(a) : "l"(p));
    return a;
}
__device__ __forceinline__ void cp16(uint32_t s, const float* g) {
    asm volatile("cp.async.cg.shared.global [%0], [%1], 16;" :: "r"(s), "l"(g) : "memory");
}
__device__ __forceinline__ void ldsm4(uint32_t* r, uint32_t a) {
    asm volatile("ldmatrix.sync.aligned.m8n8.x4.shared.b16 {%0,%1,%2,%3}, [%4];"
        : "=r"(r[0]), "=r"(r[1]), "=r"(r[2]), "=r"(r[3]) : "r"(a));
}
__device__ __forceinline__ void mma8(float* d, const uint32_t* a, uint32_t b0, uint32_t b1) {
    asm volatile("mma.sync.aligned.m16n8k8.row.col.f32.tf32.tf32.f32 "
        "{%0,%1,%2,%3}, {%4,%5,%6,%7}, {%8,%9}, {%0,%1,%2,%3};"
        : "+f"(d[0]), "+f"(d[1]), "+f"(d[2]), "+f"(d[3])
        : "r"(a[0]), "r"(a[1]), "r"(a[2]), "r"(a[3]), "r"(b0), "r"(b1));
}
__device__ __forceinline__ float tf32_rna(float v) {
    uint32_t u; asm("cvt.rna.tf32.f32 %0, %1;" : "=r"(u) : "f"(v));
    return __uint_as_float(u);
}
__device__ __forceinline__ float gp_sign(int a, int b) {
    int s = 0, aa = a >> 1;
    while (aa) { s += __popc(aa & b); aa >>= 1; }
    float sg = (s & 1) ? -1.0f : 1.0f;
    if ((a & b) & 16) sg = -sg;    // e5*e5 = -1
    return sg;
}

// ---------------- prep kernels ----------------
__global__ __launch_bounds__(256) void round_x(const float4* __restrict__ x) {
    size_t i = (size_t)blockIdx.x * 256 + threadIdx.x;
    float4 v = x[i];
    reinterpret_cast<float4*>(g_xr)[i] =
        make_float4(tf32_rna(v.x), tf32_rna(v.y), tf32_rna(v.z), tf32_rna(v.w));
}

// Bp[(o*32+kb)][(i*32+l)] = tf32(w[o][i*32 + (kb^l)]) * sign(kb^l, l)
__global__ __launch_bounds__(256) void build_bp(const float* __restrict__ w) {
    size_t idx = (size_t)blockIdx.x * 256 + threadIdx.x;
    int col = (int)(idx & (XK - 1));
    int row = (int)(idx >> 13);
    int kb = row & 31;
    int l  = col & 31;
    int j  = l ^ kb;
    float v = w[((size_t)(row >> 5) << 13) + (size_t)(col & ~31) + j];
    g_Bp[idx] = tf32_rna(v) * gp_sign(j, l);
}

// ---------------- main GEMM (HMMA tf32) + fused normalize ----------------
__device__ __forceinline__ void load_stage(uint32_t sm, const float* gA, const float* gB,
                                           int it, int tid) {
    const int k0 = it * BK;
    #pragma unroll
    for (int r = 0; r < 8; r++) {
        int slot = tid + r * 128;          // 0..1023
        int row  = slot >> 3;              // 0..127
        int c    = slot & 7;               // float4 chunk in 128B row
        uint32_t sw = (uint32_t)(row * 128 + ((c ^ (row & 7)) << 4));
        cp16(sm + sw,         gA + (size_t)row * XK + k0 + c * 4);
        cp16(sm + 16384 + sw, gB + (size_t)row * XK + k0 + c * 4);
    }
}

__global__ __launch_bounds__(128, 2)
void versor_mma(float* __restrict__ out) {
    extern __shared__ char smem[];
    const uint32_t sbase = smem_u32(smem);
    const int tid  = threadIdx.x;
    const int wid  = tid >> 5;
    const int lane = tid & 31;
    const int wm   = wid & 1;              // warp row (2)
    const int wn   = wid >> 1;             // warp col (2)

    const int mtile = blockIdx.x & 15;     // fast-varying: 16 M-tiles share B panel in L2
    const int ntile = blockIdx.x >> 4;
    const int M0 = mtile * BM;
    const int N0 = ntile * BN;

    const float* gA = g_xr + (size_t)M0 * XK;
    const float* gB = g_Bp + (size_t)N0 * XK;

    // ldmatrix per-lane geometry (tf32-as-2xb16 trick):
    //  A frag x4: lanes0-7 rows+0 kc0 | 8-15 rows+8 kc0 | 16-23 rows+0 kc1 | 24-31 rows+8 kc1
    //  B frag x4: lanes0-7 rows+0 kc0 | 8-15 rows+0 kc1 | 16-23 rows+8 kc0 | 24-31 rows+8 kc1
    const int lx   = lane & 7;
    const int rA   = wm * 64 + lx + ((lane >> 3) & 1) * 8;
    const int akb  = (lane >> 4) & 1;
    const int rB   = wn * 64 + lx + ((lane >> 4) & 1) * 8;
    const int bkb  = (lane >> 3) & 1;
    const uint32_t aRow = (uint32_t)(rA * 128);
    const uint32_t bRow = 16384u + (uint32_t)(rB * 128);

    float acc[4][8][4];
    #pragma unroll
    for (int mi = 0; mi < 4; mi++)
        #pragma unroll
        for (int nj = 0; nj < 8; nj++)
            #pragma unroll
            for (int q = 0; q < 4; q++) acc[mi][nj][q] = 0.0f;

    // prologue: fill STAGES-1 stages
    load_stage(sbase, gA, gB, 0, tid);
    asm volatile("cp.async.commit_group;" ::: "memory");
    load_stage(sbase + STAGE_BYTES, gA, gB, 1, tid);
    asm volatile("cp.async.commit_group;" ::: "memory");

    #pragma unroll 1
    for (int it = 0; it < NIT; it++) {
        asm volatile("cp.async.wait_group 1;" ::: "memory");
        __syncthreads();
        int nx = it + STAGES - 1;
        if (nx < NIT)
            load_stage(sbase + (uint32_t)(nx % STAGES) * STAGE_BYTES, gA, gB, nx, tid);
        asm volatile("cp.async.commit_group;" ::: "memory");

        const uint32_t sm = sbase + (uint32_t)(it % STAGES) * STAGE_BYTES;
        #pragma unroll
        for (int ks = 0; ks < 4; ks++) {
            const uint32_t cA = (uint32_t)(((ks * 2 + akb) ^ lx) << 4);
            const uint32_t cB = (uint32_t)(((ks * 2 + bkb) ^ lx) << 4);
            uint32_t a[4][4], b[4][4];
            #pragma unroll
            for (int mi = 0; mi < 4; mi++)
                ldsm4(a[mi], sm + aRow + (uint32_t)(mi * 2048) + cA);
            #pragma unroll
            for (int nj2 = 0; nj2 < 4; nj2++)
                ldsm4(b[nj2], sm + bRow + (uint32_t)(nj2 * 2048) + cB);
            #pragma unroll
            for (int mi = 0; mi < 4; mi++)
                #pragma unroll
                for (int nj2 = 0; nj2 < 4; nj2++) {
                    mma8(acc[mi][2 * nj2],     a[mi], b[nj2][0], b[nj2][1]);
                    mma8(acc[mi][2 * nj2 + 1], a[mi], b[nj2][2], b[nj2][3]);
                }
        }
    }

    // ---- fused epilogue: 32-col blade groups live inside one quad ----
    const int qc   = lane & 3;          // col pair within quad
    const int rofs = lane >> 2;         // row 0..7
    #pragma unroll
    for (int mi = 0; mi < 4; mi++) {
        const int row0 = M0 + wm * 64 + mi * 16 + rofs;
        #pragma unroll
        for (int g = 0; g < 2; g++) {   // two 32-col groups per warp tile
            float ss0 = 0.0f, ss1 = 0.0f;
            #pragma unroll
            for (int j = 0; j < 4; j++) {
                int nj = g * 4 + j;
                ss0 += acc[mi][nj][0] * acc[mi][nj][0] + acc[mi][nj][1] * acc[mi][nj][1];
                ss1 += acc[mi][nj][2] * acc[mi][nj][2] + acc[mi][nj][3] * acc[mi][nj][3];
            }
            ss0 += __shfl_xor_sync(0xffffffffu, ss0, 1);
            ss0 += __shfl_xor_sync(0xffffffffu, ss0, 2);
            ss1 += __shfl_xor_sync(0xffffffffu, ss1, 1);
            ss1 += __shfl_xor_sync(0xffffffffu, ss1, 2);
            const float inv0 = rsqrtf(ss0 + 1e-6f);
            const float inv1 = rsqrtf(ss1 + 1e-6f);
            #pragma unroll
            for (int j = 0; j < 4; j++) {
                int nj  = g * 4 + j;
                int col = N0 + wn * 64 + nj * 8 + 2 * qc;
                *reinterpret_cast<float2*>(out + (size_t)row0 * NOUT + col) =
                    make_float2(acc[mi][nj][0] * inv0, acc[mi][nj][1] * inv0);
                *reinterpret_cast<float2*>(out + (size_t)(row0 + 8) * NOUT + col) =
                    make_float2(acc[mi][nj][2] * inv1, acc[mi][nj][3] * inv1);
            }
        }
    }
}

// ---------------- host ----------------
extern "C" void kernel_launch(void* const* d_in, const int* in_sizes, int n_in,
                              void* d_out, int out_size) {
    const float* x = (const float*)d_in[0];   // [2048, 8192]
    const float* w = (const float*)d_in[1];   // [256, 8192]
    float* out = (float*)d_out;               // [2048, 8192] = [n][o][k]

    round_x<<<(NTOK * (size_t)XK / 4) / 256, 256>>>(reinterpret_cast<const float4*>(x));
    build_bp<<<((size_t)NOUT * XK) / 256, 256>>>(w);

    cudaFuncSetAttribute(versor_mma, cudaFuncAttributeMaxDynamicSharedMemorySize, SMEM_TOTAL);
    versor_mma<<<(NTOK / BM) * (NOUT / BN), 128, SMEM_TOTAL>>>(out);
}

// round 4
// speedup vs baseline: 17.0223x; 4.1321x over previous
#include <cuda_runtime.h>
#include <cstdint>
#include <utility>

#define NTOK 2048
#define IFEAT 256
#define OFEAT 256
#define MDIM 8192            // GEMM M = NTOK*4
#define NDIM 2048            // GEMM N = OFEAT*4 (re) + OFEAT*4 (im)
#define KDIM 2048            // GEMM K = IFEAT*4 (re) + IFEAT*4 (im)

#define BM 128
#define BN 128
#define BK 32
#define STAGES 3
#define NIT (KDIM / BK)      // 64
#define STAGE_BYTES 32768
#define SMEM_TOTAL (STAGES * STAGE_BYTES)

// ---- scratch ----
__device__ float g_A [(size_t)MDIM * KDIM];   // 64 MB: realified rep of x
__device__ float g_Bt[(size_t)NDIM * KDIM];   // 16 MB: realified rep of w (col-major wrt GEMM N)
__device__ float g_C [(size_t)MDIM * NDIM];   // 64 MB: raw GEMM result

// ================= compile-time Cl(4,1) -> M4(C) representation =================
// rho(e_A)[r][col[A][r]] = i^code[A][r]; s[A] = sign of e_A^2.
struct Rho { int col[32][4]; int code[32][4]; int s[32]; };

constexpr Rho make_rho() {
    Rho R{};
    int gc[5][4] = {}; int gv[5][4] = {};
    for (int r = 0; r < 4; r++) {
        int a = r >> 1, b = r & 1;
        gc[0][r] = r ^ 2; gv[0][r] = b ? 2 : 0;                              // s1 (x) E
        gc[1][r] = r ^ 2; gv[1][r] = ((a ? 1 : 3) + (b ? 2 : 0)) & 3;        // s2 (x) E
        gc[2][r] = r;     gv[2][r] = ((a ? 2 : 0) + (b ? 2 : 0)) & 3;        // s3 (x) E
        gc[3][r] = r ^ 1; gv[3][r] = 0;                                      // I (x) sx
        gc[4][r] = r ^ 1; gv[4][r] = b ? 2 : 0;                              // I (x) J
    }
    for (int A = 0; A < 32; A++) {
        int pc[4] = {0, 1, 2, 3}, pv[4] = {0, 0, 0, 0};
        for (int i = 0; i < 5; i++)
            if ((A >> i) & 1)
                for (int r = 0; r < 4; r++) {
                    int t = pc[r];
                    pc[r] = gc[i][t];
                    pv[r] = (pv[r] + gv[i][t]) & 3;
                }
        for (int r = 0; r < 4; r++) { R.col[A][r] = pc[r]; R.code[A][r] = pv[r]; }
        int sq = (pv[0] + pv[pc[0]]) & 3;     // code of (rho^2)[0][0]; rho^2 = s*I
        R.s[A] = (sq == 0) ? 1 : -1;
    }
    return R;
}
constexpr Rho RHO = make_rho();

// ---- template-unrolled transforms (all indices compile-time) ----
// x-side: store transposed: Lre[c][u] = Re rho(x)[u][c]
template<int A, int R>
__device__ __forceinline__ void fx1(const float* v, float (&Lre)[4][4], float (&Lim)[4][4]) {
    constexpr int c = RHO.col[A][R];
    constexpr int k = RHO.code[A][R];
    if constexpr (k == 0) Lre[c][R] += v[A];
    else if constexpr (k == 1) Lim[c][R] += v[A];
    else if constexpr (k == 2) Lre[c][R] -= v[A];
    else                       Lim[c][R] -= v[A];
}
template<int A>
__device__ __forceinline__ void fxA(const float* v, float (&Lre)[4][4], float (&Lim)[4][4]) {
    fx1<A,0>(v,Lre,Lim); fx1<A,1>(v,Lre,Lim); fx1<A,2>(v,Lre,Lim); fx1<A,3>(v,Lre,Lim);
}
template<int... As>
__device__ __forceinline__ void fxall(const float* v, float (&Lre)[4][4], float (&Lim)[4][4],
                                      std::integer_sequence<int, As...>) {
    (fxA<As>(v, Lre, Lim), ...);
}
// w-side: direct: Wre[r][c] = Re rho(w)[r][c]
template<int A, int R>
__device__ __forceinline__ void fw1(const float* v, float (&Wre)[4][4], float (&Wim)[4][4]) {
    constexpr int c = RHO.col[A][R];
    constexpr int k = RHO.code[A][R];
    if constexpr (k == 0) Wre[R][c] += v[A];
    else if constexpr (k == 1) Wim[R][c] += v[A];
    else if constexpr (k == 2) Wre[R][c] -= v[A];
    else                       Wim[R][c] -= v[A];
}
template<int A>
__device__ __forceinline__ void fwA(const float* v, float (&Wre)[4][4], float (&Wim)[4][4]) {
    fw1<A,0>(v,Wre,Wim); fw1<A,1>(v,Wre,Wim); fw1<A,2>(v,Wre,Wim); fw1<A,3>(v,Wre,Wim);
}
template<int... As>
__device__ __forceinline__ void fwall(const float* v, float (&Wre)[4][4], float (&Wim)[4][4],
                                      std::integer_sequence<int, As...>) {
    (fwA<As>(v, Wre, Wim), ...);
}
// inverse: x_A = 0.25*s_A*sum_r Re( i^code * M[col][r] ),  Mre[t][c] local
template<int A, int R>
__device__ __forceinline__ float iv1(const float (&Mre)[4][4], const float (&Mim)[4][4]) {
    constexpr int t = RHO.col[A][R];
    constexpr int k = RHO.code[A][R];
    if constexpr (k == 0) return  Mre[t][R];
    else if constexpr (k == 1) return -Mim[t][R];
    else if constexpr (k == 2) return -Mre[t][R];
    else                       return  Mim[t][R];
}
template<int A>
__device__ __forceinline__ float bladeA(const float (&Mre)[4][4], const float (&Mim)[4][4]) {
    constexpr float s = 0.25f * (float)RHO.s[A];
    return s * (iv1<A,0>(Mre,Mim) + iv1<A,1>(Mre,Mim) + iv1<A,2>(Mre,Mim) + iv1<A,3>(Mre,Mim));
}
template<int... As>
__device__ __forceinline__ void blades(float* v, const float (&Mre)[4][4], const float (&Mim)[4][4],
                                       std::integer_sequence<int, As...>) {
    ((v[As] = bladeA<As>(Mre, Mim)), ...);
}

// ================= small PTX helpers =================
__device__ __forceinline__ uint32_t smem_u32(const void* p) {
    uint32_t a;
    asm("{ .reg .u64 t; cvta.to.shared.u64 t, %1; cvt.u32.u64 %0, t; }" : "=r"(a) : "l"(p));
    return a;
}
__device__ __forceinline__ void cp16(uint32_t s, const float* g) {
    asm volatile("cp.async.cg.shared.global [%0], [%1], 16;" :: "r"(s), "l"(g) : "memory");
}
__device__ __forceinline__ void ldsm4(uint32_t* r, uint32_t a) {
    asm volatile("ldmatrix.sync.aligned.m8n8.x4.shared.b16 {%0,%1,%2,%3}, [%4];"
        : "=r"(r[0]), "=r"(r[1]), "=r"(r[2]), "=r"(r[3]) : "r"(a));
}
__device__ __forceinline__ void mma8(float* d, const uint32_t* a, uint32_t b0, uint32_t b1) {
    asm volatile("mma.sync.aligned.m16n8k8.row.col.f32.tf32.tf32.f32 "
        "{%0,%1,%2,%3}, {%4,%5,%6,%7}, {%8,%9}, {%0,%1,%2,%3};"
        : "+f"(d[0]), "+f"(d[1]), "+f"(d[2]), "+f"(d[3])
        : "r"(a[0]), "r"(a[1]), "r"(a[2]), "r"(a[3]), "r"(b0), "r"(b1));
}
__device__ __forceinline__ float tf32_rna(float v) {
    uint32_t u; asm("cvt.rna.tf32.f32 %0, %1;" : "=r"(u) : "f"(v));
    return __uint_as_float(u);
}
__device__ __forceinline__ float4 tf4(float a, float b, float c, float d) {
    return make_float4(tf32_rna(a), tf32_rna(b), tf32_rna(c), tf32_rna(d));
}

// ================= transform kernels =================
__global__ __launch_bounds__(128) void fwd_x(const float* __restrict__ x) {
    int idx = blockIdx.x * 128 + threadIdx.x;         // (n,i), i fastest
    float v[32];
    const float4* xv = reinterpret_cast<const float4*>(x) + (size_t)idx * 8;
    #pragma unroll
    for (int q = 0; q < 8; q++) {
        float4 t = xv[q];
        v[4*q] = t.x; v[4*q+1] = t.y; v[4*q+2] = t.z; v[4*q+3] = t.w;
    }
    float Lre[4][4] = {}, Lim[4][4] = {};
    fxall(v, Lre, Lim, std::make_integer_sequence<int, 32>{});
    int n = idx >> 8, i = idx & 255;
    #pragma unroll
    for (int c = 0; c < 4; c++) {
        size_t base = (size_t)(n * 4 + c) * KDIM + i * 4;
        *reinterpret_cast<float4*>(g_A + base) = tf4(Lre[c][0], Lre[c][1], Lre[c][2], Lre[c][3]);
        *reinterpret_cast<float4*>(g_A + base + 1024) = tf4(Lim[c][0], Lim[c][1], Lim[c][2], Lim[c][3]);
    }
}

__global__ __launch_bounds__(128) void fwd_w(const float* __restrict__ w) {
    int idx = blockIdx.x * 128 + threadIdx.x;         // (o,i), i fastest
    float v[32];
    const float4* wv = reinterpret_cast<const float4*>(w) + (size_t)idx * 8;
    #pragma unroll
    for (int q = 0; q < 8; q++) {
        float4 t = wv[q];
        v[4*q] = t.x; v[4*q+1] = t.y; v[4*q+2] = t.z; v[4*q+3] = t.w;
    }
    float Wre[4][4] = {}, Wim[4][4] = {};
    fwall(v, Wre, Wim, std::make_integer_sequence<int, 32>{});
    int o = idx >> 8, i = idx & 255;
    #pragma unroll
    for (int t = 0; t < 4; t++) {
        float4 re = tf4(Wre[t][0], Wre[t][1], Wre[t][2], Wre[t][3]);
        float4 im = tf4(Wim[t][0], Wim[t][1], Wim[t][2], Wim[t][3]);
        float4 nim = make_float4(-im.x, -im.y, -im.z, -im.w);
        size_t r1 = (size_t)(o * 4 + t) * KDIM + i * 4;
        size_t r2 = (size_t)(1024 + o * 4 + t) * KDIM + i * 4;
        *reinterpret_cast<float4*>(g_Bt + r1)        = re;
        *reinterpret_cast<float4*>(g_Bt + r1 + 1024) = nim;
        *reinterpret_cast<float4*>(g_Bt + r2)        = im;
        *reinterpret_cast<float4*>(g_Bt + r2 + 1024) = re;
    }
}

// ================= GEMM: C[8192x2048] = A . Bt^T  (tf32 HMMA) =================
__device__ __forceinline__ void load_stage(uint32_t sm, const float* gA, const float* gB,
                                           int it, int tid) {
    const int k0 = it * BK;
    #pragma unroll
    for (int r = 0; r < 8; r++) {
        int slot = tid + r * 128;
        int row  = slot >> 3;
        int c    = slot & 7;
        uint32_t sw = (uint32_t)(row * 128 + ((c ^ (row & 7)) << 4));
        cp16(sm + sw,         gA + (size_t)row * KDIM + k0 + c * 4);
        cp16(sm + 16384 + sw, gB + (size_t)row * KDIM + k0 + c * 4);
    }
}

__global__ __launch_bounds__(128, 2)
void versor_mma() {
    extern __shared__ char smem[];
    const uint32_t sbase = smem_u32(smem);
    const int tid  = threadIdx.x;
    const int wid  = tid >> 5;
    const int lane = tid & 31;
    const int wm   = wid & 1;
    const int wn   = wid >> 1;

    const int ntile = blockIdx.x & 15;     // 16 N-tiles (B 16MB fully L2-resident)
    const int mtile = blockIdx.x >> 4;     // 64 M-tiles
    const int M0 = mtile * BM;
    const int N0 = ntile * BN;

    const float* gA = g_A  + (size_t)M0 * KDIM;
    const float* gB = g_Bt + (size_t)N0 * KDIM;

    const int lx  = lane & 7;
    const int rA  = wm * 64 + lx + ((lane >> 3) & 1) * 8;
    const int akb = (lane >> 4) & 1;
    const int rB  = wn * 64 + lx + ((lane >> 4) & 1) * 8;
    const int bkb = (lane >> 3) & 1;
    const uint32_t aRow = (uint32_t)(rA * 128);
    const uint32_t bRow = 16384u + (uint32_t)(rB * 128);

    float acc[4][8][4];
    #pragma unroll
    for (int mi = 0; mi < 4; mi++)
        #pragma unroll
        for (int nj = 0; nj < 8; nj++)
            #pragma unroll
            for (int q = 0; q < 4; q++) acc[mi][nj][q] = 0.0f;

    load_stage(sbase, gA, gB, 0, tid);
    asm volatile("cp.async.commit_group;" ::: "memory");
    load_stage(sbase + STAGE_BYTES, gA, gB, 1, tid);
    asm volatile("cp.async.commit_group;" ::: "memory");

    #pragma unroll 1
    for (int it = 0; it < NIT; it++) {
        asm volatile("cp.async.wait_group 1;" ::: "memory");
        __syncthreads();
        int nx = it + STAGES - 1;
        if (nx < NIT)
            load_stage(sbase + (uint32_t)(nx % STAGES) * STAGE_BYTES, gA, gB, nx, tid);
        asm volatile("cp.async.commit_group;" ::: "memory");

        const uint32_t sm = sbase + (uint32_t)(it % STAGES) * STAGE_BYTES;
        #pragma unroll
        for (int ks = 0; ks < 4; ks++) {
            const uint32_t cA = (uint32_t)(((ks * 2 + akb) ^ lx) << 4);
            const uint32_t cB = (uint32_t)(((ks * 2 + bkb) ^ lx) << 4);
            uint32_t a[4][4], b[4][4];
            #pragma unroll
            for (int mi = 0; mi < 4; mi++)
                ldsm4(a[mi], sm + aRow + (uint32_t)(mi * 2048) + cA);
            #pragma unroll
            for (int nj2 = 0; nj2 < 4; nj2++)
                ldsm4(b[nj2], sm + bRow + (uint32_t)(nj2 * 2048) + cB);
            #pragma unroll
            for (int mi = 0; mi < 4; mi++)
                #pragma unroll
                for (int nj2 = 0; nj2 < 4; nj2++) {
                    mma8(acc[mi][2 * nj2],     a[mi], b[nj2][0], b[nj2][1]);
                    mma8(acc[mi][2 * nj2 + 1], a[mi], b[nj2][2], b[nj2][3]);
                }
        }
    }

    const int qc   = lane & 3;
    const int rofs = lane >> 2;
    #pragma unroll
    for (int mi = 0; mi < 4; mi++) {
        const int row0 = M0 + wm * 64 + mi * 16 + rofs;
        #pragma unroll
        for (int nj = 0; nj < 8; nj++) {
            const int col = N0 + wn * 64 + nj * 8 + 2 * qc;
            *reinterpret_cast<float2*>(g_C + (size_t)row0 * NDIM + col) =
                make_float2(acc[mi][nj][0], acc[mi][nj][1]);
            *reinterpret_cast<float2*>(g_C + (size_t)(row0 + 8) * NDIM + col) =
                make_float2(acc[mi][nj][2], acc[mi][nj][3]);
        }
    }
}

// ================= inverse transform + normalize =================
__global__ __launch_bounds__(256) void inv_norm(float* __restrict__ out) {
    int idx = blockIdx.x * 256 + threadIdx.x;     // (n,o), o fastest
    int n = idx >> 8, o = idx & 255;
    float Mre[4][4], Mim[4][4];
    #pragma unroll
    for (int c = 0; c < 4; c++) {
        const float* row = g_C + (size_t)(n * 4 + c) * NDIM + o * 4;
        float4 re = *reinterpret_cast<const float4*>(row);
        float4 im = *reinterpret_cast<const float4*>(row + 1024);
        Mre[0][c] = re.x; Mre[1][c] = re.y; Mre[2][c] = re.z; Mre[3][c] = re.w;
        Mim[0][c] = im.x; Mim[1][c] = im.y; Mim[2][c] = im.z; Mim[3][c] = im.w;
    }
    float v[32];
    blades(v, Mre, Mim, std::make_integer_sequence<int, 32>{});
    float ss = 1e-6f;
    #pragma unroll
    for (int k = 0; k < 32; k++) ss += v[k] * v[k];
    float inv = rsqrtf(ss);
    float4* dst = reinterpret_cast<float4*>(out + (size_t)idx * 32);
    #pragma unroll
    for (int q = 0; q < 8; q++)
        dst[q] = make_float4(v[4*q] * inv, v[4*q+1] * inv, v[4*q+2] * inv, v[4*q+3] * inv);
}

// ================= host =================
extern "C" void kernel_launch(void* const* d_in, const int* in_sizes, int n_in,
                              void* d_out, int out_size) {
    const float* x = (const float*)d_in[0];   // [2048, 256, 32]
    const float* w = (const float*)d_in[1];   // [256, 256, 32]
    float* out = (float*)d_out;               // [2048, 256, 32]

    fwd_x<<<(NTOK * IFEAT) / 128, 128>>>(x);
    fwd_w<<<(OFEAT * IFEAT) / 128, 128>>>(w);

    cudaFuncSetAttribute(versor_mma, cudaFuncAttributeMaxDynamicSharedMemorySize, SMEM_TOTAL);
    versor_mma<<<(MDIM / BM) * (NDIM / BN), 128, SMEM_TOTAL>>>();

    inv_norm<<<(NTOK * OFEAT) / 256, 256>>>(out);
}

// round 5
// speedup vs baseline: 20.3250x; 1.1940x over previous
#include <cuda_runtime.h>
#include <cstdint>
#include <utility>

#define NTOK 2048
#define IFEAT 256
#define OFEAT 256
#define MDIM 8192            // GEMM M = NTOK*4
#define NC   1024            // complex GEMM N (real-valued operands)
#define KC   1024            // complex GEMM K

#define BM 128
#define BN 128
#define BK 32
#define STAGES 3
#define NIT (KC / BK)        // 32
#define STAGE_BYTES 32768
#define SMEM_TOTAL (STAGES * STAGE_BYTES)

#define A_CHUNK ((size_t)MDIM * KC)   // 8M floats
#define B_CHUNK ((size_t)NC * KC)
#define P_CHUNK ((size_t)MDIM * NC)

// ---- scratch ----
__device__ float g_A[3 * A_CHUNK];   // 96 MB: Xre, Xim, Xre+Xim  (tf32-rounded)
__device__ float g_B[3 * B_CHUNK];   // 12 MB: Wre, Wim, Wre+Wim
__device__ float g_P[3 * P_CHUNK];   // 96 MB: P1, P2, P3

// ================= compile-time Cl(4,1) -> M4(C) representation =================
struct Rho { int col[32][4]; int code[32][4]; int s[32]; };

constexpr Rho make_rho() {
    Rho R{};
    int gc[5][4] = {}; int gv[5][4] = {};
    for (int r = 0; r < 4; r++) {
        int a = r >> 1, b = r & 1;
        gc[0][r] = r ^ 2; gv[0][r] = b ? 2 : 0;                              // s1 (x) E
        gc[1][r] = r ^ 2; gv[1][r] = ((a ? 1 : 3) + (b ? 2 : 0)) & 3;        // s2 (x) E
        gc[2][r] = r;     gv[2][r] = ((a ? 2 : 0) + (b ? 2 : 0)) & 3;        // s3 (x) E
        gc[3][r] = r ^ 1; gv[3][r] = 0;                                      // I (x) sx
        gc[4][r] = r ^ 1; gv[4][r] = b ? 2 : 0;                              // I (x) J
    }
    for (int A = 0; A < 32; A++) {
        int pc[4] = {0, 1, 2, 3}, pv[4] = {0, 0, 0, 0};
        for (int i = 0; i < 5; i++)
            if ((A >> i) & 1)
                for (int r = 0; r < 4; r++) {
                    int t = pc[r];
                    pc[r] = gc[i][t];
                    pv[r] = (pv[r] + gv[i][t]) & 3;
                }
        for (int r = 0; r < 4; r++) { R.col[A][r] = pc[r]; R.code[A][r] = pv[r]; }
        int sq = (pv[0] + pv[pc[0]]) & 3;
        R.s[A] = (sq == 0) ? 1 : -1;
    }
    return R;
}
constexpr Rho RHO = make_rho();

// ---- template-unrolled transforms ----
template<int A, int R>
__device__ __forceinline__ void fx1(const float* v, float (&Lre)[4][4], float (&Lim)[4][4]) {
    constexpr int c = RHO.col[A][R];
    constexpr int k = RHO.code[A][R];
    if constexpr (k == 0) Lre[c][R] += v[A];
    else if constexpr (k == 1) Lim[c][R] += v[A];
    else if constexpr (k == 2) Lre[c][R] -= v[A];
    else                       Lim[c][R] -= v[A];
}
template<int A>
__device__ __forceinline__ void fxA(const float* v, float (&Lre)[4][4], float (&Lim)[4][4]) {
    fx1<A,0>(v,Lre,Lim); fx1<A,1>(v,Lre,Lim); fx1<A,2>(v,Lre,Lim); fx1<A,3>(v,Lre,Lim);
}
template<int... As>
__device__ __forceinline__ void fxall(const float* v, float (&Lre)[4][4], float (&Lim)[4][4],
                                      std::integer_sequence<int, As...>) {
    (fxA<As>(v, Lre, Lim), ...);
}
template<int A, int R>
__device__ __forceinline__ void fw1(const float* v, float (&Wre)[4][4], float (&Wim)[4][4]) {
    constexpr int c = RHO.col[A][R];
    constexpr int k = RHO.code[A][R];
    if constexpr (k == 0) Wre[R][c] += v[A];
    else if constexpr (k == 1) Wim[R][c] += v[A];
    else if constexpr (k == 2) Wre[R][c] -= v[A];
    else                       Wim[R][c] -= v[A];
}
template<int A>
__device__ __forceinline__ void fwA(const float* v, float (&Wre)[4][4], float (&Wim)[4][4]) {
    fw1<A,0>(v,Wre,Wim); fw1<A,1>(v,Wre,Wim); fw1<A,2>(v,Wre,Wim); fw1<A,3>(v,Wre,Wim);
}
template<int... As>
__device__ __forceinline__ void fwall(const float* v, float (&Wre)[4][4], float (&Wim)[4][4],
                                      std::integer_sequence<int, As...>) {
    (fwA<As>(v, Wre, Wim), ...);
}
template<int A, int R>
__device__ __forceinline__ float iv1(const float (&Mre)[4][4], const float (&Mim)[4][4]) {
    constexpr int t = RHO.col[A][R];
    constexpr int k = RHO.code[A][R];
    if constexpr (k == 0) return  Mre[t][R];
    else if constexpr (k == 1) return -Mim[t][R];
    else if constexpr (k == 2) return -Mre[t][R];
    else                       return  Mim[t][R];
}
template<int A>
__device__ __forceinline__ float bladeA(const float (&Mre)[4][4], const float (&Mim)[4][4]) {
    constexpr float s = 0.25f * (float)RHO.s[A];
    return s * (iv1<A,0>(Mre,Mim) + iv1<A,1>(Mre,Mim) + iv1<A,2>(Mre,Mim) + iv1<A,3>(Mre,Mim));
}
template<int... As>
__device__ __forceinline__ void blades(float* v, const float (&Mre)[4][4], const float (&Mim)[4][4],
                                       std::integer_sequence<int, As...>) {
    ((v[As] = bladeA<As>(Mre, Mim)), ...);
}

// ================= PTX helpers =================
__device__ __forceinline__ uint32_t smem_u32(const void* p) {
    uint32_t a;
    asm("{ .reg .u64 t; cvta.to.shared.u64 t, %1; cvt.u32.u64 %0, t; }" : "=r"(a) : "l"(p));
    return a;
}
__device__ __forceinline__ void cp16(uint32_t s, const float* g) {
    asm volatile("cp.async.cg.shared.global [%0], [%1], 16;" :: "r"(s), "l"(g) : "memory");
}
__device__ __forceinline__ void ldsm4(uint32_t* r, uint32_t a) {
    asm volatile("ldmatrix.sync.aligned.m8n8.x4.shared.b16 {%0,%1,%2,%3}, [%4];"
        : "=r"(r[0]), "=r"(r[1]), "=r"(r[2]), "=r"(r[3]) : "r"(a));
}
__device__ __forceinline__ void mma8(float* d, const uint32_t* a, uint32_t b0, uint32_t b1) {
    asm volatile("mma.sync.aligned.m16n8k8.row.col.f32.tf32.tf32.f32 "
        "{%0,%1,%2,%3}, {%4,%5,%6,%7}, {%8,%9}, {%0,%1,%2,%3};"
        : "+f"(d[0]), "+f"(d[1]), "+f"(d[2]), "+f"(d[3])
        : "r"(a[0]), "r"(a[1]), "r"(a[2]), "r"(a[3]), "r"(b0), "r"(b1));
}
__device__ __forceinline__ float tf32_rna(float v) {
    uint32_t u; asm("cvt.rna.tf32.f32 %0, %1;" : "=r"(u) : "f"(v));
    return __uint_as_float(u);
}
__device__ __forceinline__ float4 tf4(float a, float b, float c, float d) {
    return make_float4(tf32_rna(a), tf32_rna(b), tf32_rna(c), tf32_rna(d));
}

// ================= transform kernels =================
__global__ __launch_bounds__(128) void fwd_x(const float* __restrict__ x) {
    int idx = blockIdx.x * 128 + threadIdx.x;         // (n,i), i fastest
    float v[32];
    const float4* xv = reinterpret_cast<const float4*>(x) + (size_t)idx * 8;
    #pragma unroll
    for (int q = 0; q < 8; q++) {
        float4 t = xv[q];
        v[4*q] = t.x; v[4*q+1] = t.y; v[4*q+2] = t.z; v[4*q+3] = t.w;
    }
    float Lre[4][4] = {}, Lim[4][4] = {};
    fxall(v, Lre, Lim, std::make_integer_sequence<int, 32>{});
    int n = idx >> 8, i = idx & 255;
    #pragma unroll
    for (int c = 0; c < 4; c++) {
        size_t base = (size_t)(n * 4 + c) * KC + i * 4;
        *reinterpret_cast<float4*>(g_A + base) =
            tf4(Lre[c][0], Lre[c][1], Lre[c][2], Lre[c][3]);
        *reinterpret_cast<float4*>(g_A + A_CHUNK + base) =
            tf4(Lim[c][0], Lim[c][1], Lim[c][2], Lim[c][3]);
        *reinterpret_cast<float4*>(g_A + 2 * A_CHUNK + base) =
            tf4(Lre[c][0] + Lim[c][0], Lre[c][1] + Lim[c][1],
                Lre[c][2] + Lim[c][2], Lre[c][3] + Lim[c][3]);
    }
}

__global__ __launch_bounds__(128) void fwd_w(const float* __restrict__ w) {
    int idx = blockIdx.x * 128 + threadIdx.x;         // (o,i), i fastest
    float v[32];
    const float4* wv = reinterpret_cast<const float4*>(w) + (size_t)idx * 8;
    #pragma unroll
    for (int q = 0; q < 8; q++) {
        float4 t = wv[q];
        v[4*q] = t.x; v[4*q+1] = t.y; v[4*q+2] = t.z; v[4*q+3] = t.w;
    }
    float Wre[4][4] = {}, Wim[4][4] = {};
    fwall(v, Wre, Wim, std::make_integer_sequence<int, 32>{});
    int o = idx >> 8, i = idx & 255;
    #pragma unroll
    for (int t = 0; t < 4; t++) {
        size_t base = (size_t)(o * 4 + t) * KC + i * 4;
        *reinterpret_cast<float4*>(g_B + base) =
            tf4(Wre[t][0], Wre[t][1], Wre[t][2], Wre[t][3]);
        *reinterpret_cast<float4*>(g_B + B_CHUNK + base) =
            tf4(Wim[t][0], Wim[t][1], Wim[t][2], Wim[t][3]);
        *reinterpret_cast<float4*>(g_B + 2 * B_CHUNK + base) =
            tf4(Wre[t][0] + Wim[t][0], Wre[t][1] + Wim[t][1],
                Wre[t][2] + Wim[t][2], Wre[t][3] + Wim[t][3]);
    }
}

// ================= GEMM: P_z[8192x1024] = A_z . B_z^T  (tf32 HMMA) =================
__device__ __forceinline__ void load_stage(uint32_t sm, const float* gA, const float* gB,
                                           int it, int tid) {
    const int k0 = it * BK;
    #pragma unroll
    for (int r = 0; r < 8; r++) {
        int slot = tid + r * 128;
        int row  = slot >> 3;
        int c    = slot & 7;
        uint32_t sw = (uint32_t)(row * 128 + ((c ^ (row & 7)) << 4));
        cp16(sm + sw,         gA + (size_t)row * KC + k0 + c * 4);
        cp16(sm + 16384 + sw, gB + (size_t)row * KC + k0 + c * 4);
    }
}

__global__ __launch_bounds__(128, 2)
void versor_mma() {
    extern __shared__ char smem[];
    const uint32_t sbase = smem_u32(smem);
    const int tid  = threadIdx.x;
    const int wid  = tid >> 5;
    const int lane = tid & 31;
    const int wm   = wid & 1;
    const int wn   = wid >> 1;

    const int z  = blockIdx.z;             // which Gauss product
    const int N0 = blockIdx.x * BN;        // fast: 8 n-tiles share A panel in L2
    const int M0 = blockIdx.y * BM;

    const float* gA = g_A + (size_t)z * A_CHUNK + (size_t)M0 * KC;
    const float* gB = g_B + (size_t)z * B_CHUNK + (size_t)N0 * KC;
    float* gP = g_P + (size_t)z * P_CHUNK;

    const int lx  = lane & 7;
    const int rA  = wm * 64 + lx + ((lane >> 3) & 1) * 8;
    const int akb = (lane >> 4) & 1;
    const int rB  = wn * 64 + lx + ((lane >> 4) & 1) * 8;
    const int bkb = (lane >> 3) & 1;
    const uint32_t aRow = (uint32_t)(rA * 128);
    const uint32_t bRow = 16384u + (uint32_t)(rB * 128);

    float acc[4][8][4];
    #pragma unroll
    for (int mi = 0; mi < 4; mi++)
        #pragma unroll
        for (int nj = 0; nj < 8; nj++)
            #pragma unroll
            for (int q = 0; q < 4; q++) acc[mi][nj][q] = 0.0f;

    load_stage(sbase, gA, gB, 0, tid);
    asm volatile("cp.async.commit_group;" ::: "memory");
    load_stage(sbase + STAGE_BYTES, gA, gB, 1, tid);
    asm volatile("cp.async.commit_group;" ::: "memory");

    #pragma unroll 1
    for (int it = 0; it < NIT; it++) {
        asm volatile("cp.async.wait_group 1;" ::: "memory");
        __syncthreads();
        int nx = it + STAGES - 1;
        if (nx < NIT)
            load_stage(sbase + (uint32_t)(nx % STAGES) * STAGE_BYTES, gA, gB, nx, tid);
        asm volatile("cp.async.commit_group;" ::: "memory");

        const uint32_t sm = sbase + (uint32_t)(it % STAGES) * STAGE_BYTES;
        #pragma unroll
        for (int ks = 0; ks < 4; ks++) {
            const uint32_t cA = (uint32_t)(((ks * 2 + akb) ^ lx) << 4);
            const uint32_t cB = (uint32_t)(((ks * 2 + bkb) ^ lx) << 4);
            uint32_t a[4][4], b[4][4];
            #pragma unroll
            for (int mi = 0; mi < 4; mi++)
                ldsm4(a[mi], sm + aRow + (uint32_t)(mi * 2048) + cA);
            #pragma unroll
            for (int nj2 = 0; nj2 < 4; nj2++)
                ldsm4(b[nj2], sm + bRow + (uint32_t)(nj2 * 2048) + cB);
            #pragma unroll
            for (int mi = 0; mi < 4; mi++)
                #pragma unroll
                for (int nj2 = 0; nj2 < 4; nj2++) {
                    mma8(acc[mi][2 * nj2],     a[mi], b[nj2][0], b[nj2][1]);
                    mma8(acc[mi][2 * nj2 + 1], a[mi], b[nj2][2], b[nj2][3]);
                }
        }
    }

    const int qc   = lane & 3;
    const int rofs = lane >> 2;
    #pragma unroll
    for (int mi = 0; mi < 4; mi++) {
        const int row0 = M0 + wm * 64 + mi * 16 + rofs;
        #pragma unroll
        for (int nj = 0; nj < 8; nj++) {
            const int col = N0 + wn * 64 + nj * 8 + 2 * qc;
            *reinterpret_cast<float2*>(gP + (size_t)row0 * NC + col) =
                make_float2(acc[mi][nj][0], acc[mi][nj][1]);
            *reinterpret_cast<float2*>(gP + (size_t)(row0 + 8) * NC + col) =
                make_float2(acc[mi][nj][2], acc[mi][nj][3]);
        }
    }
}

// ================= Gauss combine + inverse transform + normalize =================
__global__ __launch_bounds__(256) void inv_norm(float* __restrict__ out) {
    int idx = blockIdx.x * 256 + threadIdx.x;     // (n,o), o fastest
    int n = idx >> 8, o = idx & 255;
    float Mre[4][4], Mim[4][4];
    #pragma unroll
    for (int c = 0; c < 4; c++) {
        size_t off = (size_t)(n * 4 + c) * NC + o * 4;
        float4 p1 = *reinterpret_cast<const float4*>(g_P + off);
        float4 p2 = *reinterpret_cast<const float4*>(g_P + P_CHUNK + off);
        float4 p3 = *reinterpret_cast<const float4*>(g_P + 2 * P_CHUNK + off);
        // Re = P1 - P2 ; Im = P3 - P1 - P2
        Mre[0][c] = p1.x - p2.x; Mim[0][c] = p3.x - p1.x - p2.x;
        Mre[1][c] = p1.y - p2.y; Mim[1][c] = p3.y - p1.y - p2.y;
        Mre[2][c] = p1.z - p2.z; Mim[2][c] = p3.z - p1.z - p2.z;
        Mre[3][c] = p1.w - p2.w; Mim[3][c] = p3.w - p1.w - p2.w;
    }
    float v[32];
    blades(v, Mre, Mim, std::make_integer_sequence<int, 32>{});
    float ss = 1e-6f;
    #pragma unroll
    for (int k = 0; k < 32; k++) ss += v[k] * v[k];
    float inv = rsqrtf(ss);
    float4* dst = reinterpret_cast<float4*>(out + (size_t)idx * 32);
    #pragma unroll
    for (int q = 0; q < 8; q++)
        dst[q] = make_float4(v[4*q] * inv, v[4*q+1] * inv, v[4*q+2] * inv, v[4*q+3] * inv);
}

// ================= host =================
extern "C" void kernel_launch(void* const* d_in, const int* in_sizes, int n_in,
                              void* d_out, int out_size) {
    const float* x = (const float*)d_in[0];   // [2048, 256, 32]
    const float* w = (const float*)d_in[1];   // [256, 256, 32]
    float* out = (float*)d_out;               // [2048, 256, 32]

    fwd_x<<<(NTOK * IFEAT) / 128, 128>>>(x);
    fwd_w<<<(OFEAT * IFEAT) / 128, 128>>>(w);

    cudaFuncSetAttribute(versor_mma, cudaFuncAttributeMaxDynamicSharedMemorySize, SMEM_TOTAL);
    dim3 grid(NC / BN, MDIM / BM, 3);
    versor_mma<<<grid, 128, SMEM_TOTAL>>>();

    inv_norm<<<(NTOK * OFEAT) / 256, 256>>>(out);
}

// round 6
// speedup vs baseline: 33.4140x; 1.6440x over previous
#include <cuda_runtime.h>
#include <cuda_fp16.h>
#include <cstdint>
#include <utility>

#define NTOK 2048
#define IFEAT 256
#define OFEAT 256
#define MDIM 8192            // GEMM M = NTOK*4
#define NC   1024            // complex GEMM N
#define KC   1024            // complex GEMM K

#define BM 128
#define BN 128
#define BK 64                // 64 halfs = 128 B per smem row
#define STAGES 3
#define NIT (KC / BK)        // 16
#define STAGE_BYTES 32768    // A 16KB + B 16KB
#define SMEM_TOTAL (STAGES * STAGE_BYTES)

#define A_CHUNK ((size_t)MDIM * KC)   // halfs
#define B_CHUNK ((size_t)NC * KC)
#define P_CHUNK ((size_t)MDIM * NC)   // floats

// ---- scratch ----
__device__ __half g_A[3 * A_CHUNK];   // 48 MB: Xre, Xim, Xre+Xim  (fp16)
__device__ __half g_B[3 * B_CHUNK];   // 6 MB:  Wre, Wim, Wre+Wim
__device__ float  g_P[3 * P_CHUNK];   // 96 MB: P1, P2, P3 (fp32)

// ================= compile-time Cl(4,1) -> M4(C) representation =================
struct Rho { int col[32][4]; int code[32][4]; int s[32]; };

constexpr Rho make_rho() {
    Rho R{};
    int gc[5][4] = {}; int gv[5][4] = {};
    for (int r = 0; r < 4; r++) {
        int a = r >> 1, b = r & 1;
        gc[0][r] = r ^ 2; gv[0][r] = b ? 2 : 0;                              // s1 (x) E
        gc[1][r] = r ^ 2; gv[1][r] = ((a ? 1 : 3) + (b ? 2 : 0)) & 3;        // s2 (x) E
        gc[2][r] = r;     gv[2][r] = ((a ? 2 : 0) + (b ? 2 : 0)) & 3;        // s3 (x) E
        gc[3][r] = r ^ 1; gv[3][r] = 0;                                      // I (x) sx
        gc[4][r] = r ^ 1; gv[4][r] = b ? 2 : 0;                              // I (x) J
    }
    for (int A = 0; A < 32; A++) {
        int pc[4] = {0, 1, 2, 3}, pv[4] = {0, 0, 0, 0};
        for (int i = 0; i < 5; i++)
            if ((A >> i) & 1)
                for (int r = 0; r < 4; r++) {
                    int t = pc[r];
                    pc[r] = gc[i][t];
                    pv[r] = (pv[r] + gv[i][t]) & 3;
                }
        for (int r = 0; r < 4; r++) { R.col[A][r] = pc[r]; R.code[A][r] = pv[r]; }
        int sq = (pv[0] + pv[pc[0]]) & 3;
        R.s[A] = (sq == 0) ? 1 : -1;
    }
    return R;
}
constexpr Rho RHO = make_rho();

// ---- template-unrolled transforms ----
template<int A, int R>
__device__ __forceinline__ void fx1(const float* v, float (&Lre)[4][4], float (&Lim)[4][4]) {
    constexpr int c = RHO.col[A][R];
    constexpr int k = RHO.code[A][R];
    if constexpr (k == 0) Lre[c][R] += v[A];
    else if constexpr (k == 1) Lim[c][R] += v[A];
    else if constexpr (k == 2) Lre[c][R] -= v[A];
    else                       Lim[c][R] -= v[A];
}
template<int A>
__device__ __forceinline__ void fxA(const float* v, float (&Lre)[4][4], float (&Lim)[4][4]) {
    fx1<A,0>(v,Lre,Lim); fx1<A,1>(v,Lre,Lim); fx1<A,2>(v,Lre,Lim); fx1<A,3>(v,Lre,Lim);
}
template<int... As>
__device__ __forceinline__ void fxall(const float* v, float (&Lre)[4][4], float (&Lim)[4][4],
                                      std::integer_sequence<int, As...>) {
    (fxA<As>(v, Lre, Lim), ...);
}
template<int A, int R>
__device__ __forceinline__ void fw1(const float* v, float (&Wre)[4][4], float (&Wim)[4][4]) {
    constexpr int c = RHO.col[A][R];
    constexpr int k = RHO.code[A][R];
    if constexpr (k == 0) Wre[R][c] += v[A];
    else if constexpr (k == 1) Wim[R][c] += v[A];
    else if constexpr (k == 2) Wre[R][c] -= v[A];
    else                       Wim[R][c] -= v[A];
}
template<int A>
__device__ __forceinline__ void fwA(const float* v, float (&Wre)[4][4], float (&Wim)[4][4]) {
    fw1<A,0>(v,Wre,Wim); fw1<A,1>(v,Wre,Wim); fw1<A,2>(v,Wre,Wim); fw1<A,3>(v,Wre,Wim);
}
template<int... As>
__device__ __forceinline__ void fwall(const float* v, float (&Wre)[4][4], float (&Wim)[4][4],
                                      std::integer_sequence<int, As...>) {
    (fwA<As>(v, Wre, Wim), ...);
}
template<int A, int R>
__device__ __forceinline__ float iv1(const float (&Mre)[4][4], const float (&Mim)[4][4]) {
    constexpr int t = RHO.col[A][R];
    constexpr int k = RHO.code[A][R];
    if constexpr (k == 0) return  Mre[t][R];
    else if constexpr (k == 1) return -Mim[t][R];
    else if constexpr (k == 2) return -Mre[t][R];
    else                       return  Mim[t][R];
}
template<int A>
__device__ __forceinline__ float bladeA(const float (&Mre)[4][4], const float (&Mim)[4][4]) {
    constexpr float s = 0.25f * (float)RHO.s[A];
    return s * (iv1<A,0>(Mre,Mim) + iv1<A,1>(Mre,Mim) + iv1<A,2>(Mre,Mim) + iv1<A,3>(Mre,Mim));
}
template<int... As>
__device__ __forceinline__ void blades(float* v, const float (&Mre)[4][4], const float (&Mim)[4][4],
                                       std::integer_sequence<int, As...>) {
    ((v[As] = bladeA<As>(Mre, Mim)), ...);
}

// ================= PTX helpers =================
__device__ __forceinline__ uint32_t smem_u32(const void* p) {
    uint32_t a;
    asm("{ .reg .u64 t; cvta.to.shared.u64 t, %1; cvt.u32.u64 %0, t; }" : "=r"(a) : "l"(p));
    return a;
}
__device__ __forceinline__ void cp16(uint32_t s, const void* g) {
    asm volatile("cp.async.cg.shared.global [%0], [%1], 16;" :: "r"(s), "l"(g) : "memory");
}
__device__ __forceinline__ void ldsm4(uint32_t* r, uint32_t a) {
    asm volatile("ldmatrix.sync.aligned.m8n8.x4.shared.b16 {%0,%1,%2,%3}, [%4];"
        : "=r"(r[0]), "=r"(r[1]), "=r"(r[2]), "=r"(r[3]) : "r"(a));
}
__device__ __forceinline__ void mma16(float* d, const uint32_t* a, uint32_t b0, uint32_t b1) {
    asm volatile("mma.sync.aligned.m16n8k16.row.col.f32.f16.f16.f32 "
        "{%0,%1,%2,%3}, {%4,%5,%6,%7}, {%8,%9}, {%0,%1,%2,%3};"
        : "+f"(d[0]), "+f"(d[1]), "+f"(d[2]), "+f"(d[3])
        : "r"(a[0]), "r"(a[1]), "r"(a[2]), "r"(a[3]), "r"(b0), "r"(b1));
}
// pack 4 floats -> 4 halfs (rn) as uint2
__device__ __forceinline__ uint2 h4(float a, float b, float c, float d) {
    __half2 lo = __floats2half2_rn(a, b);
    __half2 hi = __floats2half2_rn(c, d);
    uint2 r;
    r.x = *reinterpret_cast<uint32_t*>(&lo);
    r.y = *reinterpret_cast<uint32_t*>(&hi);
    return r;
}

// ================= transform kernels =================
__global__ __launch_bounds__(128) void fwd_x(const float* __restrict__ x) {
    int idx = blockIdx.x * 128 + threadIdx.x;         // (n,i), i fastest
    float v[32];
    const float4* xv = reinterpret_cast<const float4*>(x) + (size_t)idx * 8;
    #pragma unroll
    for (int q = 0; q < 8; q++) {
        float4 t = xv[q];
        v[4*q] = t.x; v[4*q+1] = t.y; v[4*q+2] = t.z; v[4*q+3] = t.w;
    }
    float Lre[4][4] = {}, Lim[4][4] = {};
    fxall(v, Lre, Lim, std::make_integer_sequence<int, 32>{});
    int n = idx >> 8, i = idx & 255;
    #pragma unroll
    for (int c = 0; c < 4; c++) {
        size_t base = (size_t)(n * 4 + c) * KC + i * 4;
        *reinterpret_cast<uint2*>(g_A + base) =
            h4(Lre[c][0], Lre[c][1], Lre[c][2], Lre[c][3]);
        *reinterpret_cast<uint2*>(g_A + A_CHUNK + base) =
            h4(Lim[c][0], Lim[c][1], Lim[c][2], Lim[c][3]);
        *reinterpret_cast<uint2*>(g_A + 2 * A_CHUNK + base) =
            h4(Lre[c][0] + Lim[c][0], Lre[c][1] + Lim[c][1],
               Lre[c][2] + Lim[c][2], Lre[c][3] + Lim[c][3]);
    }
}

__global__ __launch_bounds__(128) void fwd_w(const float* __restrict__ w) {
    int idx = blockIdx.x * 128 + threadIdx.x;         // (o,i), i fastest
    float v[32];
    const float4* wv = reinterpret_cast<const float4*>(w) + (size_t)idx * 8;
    #pragma unroll
    for (int q = 0; q < 8; q++) {
        float4 t = wv[q];
        v[4*q] = t.x; v[4*q+1] = t.y; v[4*q+2] = t.z; v[4*q+3] = t.w;
    }
    float Wre[4][4] = {}, Wim[4][4] = {};
    fwall(v, Wre, Wim, std::make_integer_sequence<int, 32>{});
    int o = idx >> 8, i = idx & 255;
    #pragma unroll
    for (int t = 0; t < 4; t++) {
        size_t base = (size_t)(o * 4 + t) * KC + i * 4;
        *reinterpret_cast<uint2*>(g_B + base) =
            h4(Wre[t][0], Wre[t][1], Wre[t][2], Wre[t][3]);
        *reinterpret_cast<uint2*>(g_B + B_CHUNK + base) =
            h4(Wim[t][0], Wim[t][1], Wim[t][2], Wim[t][3]);
        *reinterpret_cast<uint2*>(g_B + 2 * B_CHUNK + base) =
            h4(Wre[t][0] + Wim[t][0], Wre[t][1] + Wim[t][1],
               Wre[t][2] + Wim[t][2], Wre[t][3] + Wim[t][3]);
    }
}

// ================= GEMM: P_z[8192x1024] = A_z . B_z^T  (fp16 HMMA, f32 acc) =================
__device__ __forceinline__ void load_stage(uint32_t sm, const __half* gA, const __half* gB,
                                           int it, int tid) {
    const int k0 = it * BK;
    #pragma unroll
    for (int r = 0; r < 8; r++) {
        int slot = tid + r * 128;          // 0..1023
        int row  = slot >> 3;              // 0..127
        int c    = slot & 7;               // 16B chunk within 128B row
        uint32_t sw = (uint32_t)(row * 128 + ((c ^ (row & 7)) << 4));
        cp16(sm + sw,         gA + (size_t)row * KC + k0 + c * 8);
        cp16(sm + 16384 + sw, gB + (size_t)row * KC + k0 + c * 8);
    }
}

__global__ __launch_bounds__(128, 2)
void versor_mma() {
    extern __shared__ char smem[];
    const uint32_t sbase = smem_u32(smem);
    const int tid  = threadIdx.x;
    const int wid  = tid >> 5;
    const int lane = tid & 31;
    const int wm   = wid & 1;
    const int wn   = wid >> 1;

    const int z  = blockIdx.z;             // Gauss product index
    const int N0 = blockIdx.x * BN;
    const int M0 = blockIdx.y * BM;

    const __half* gA = g_A + (size_t)z * A_CHUNK + (size_t)M0 * KC;
    const __half* gB = g_B + (size_t)z * B_CHUNK + (size_t)N0 * KC;
    float* gP = g_P + (size_t)z * P_CHUNK;

    // ldmatrix geometry (b16, m16n8k16 canonical):
    //  A x4: lanes0-7 rows+0 | 8-15 rows+8 | 16-23 rows+0,k+8 | 24-31 rows+8,k+8
    //  B x4: lanes0-7 n+0,k0 | 8-15 n+0,k+8 | 16-23 n+8,k0   | 24-31 n+8,k+8
    const int lx  = lane & 7;
    const int rA  = wm * 64 + lx + ((lane >> 3) & 1) * 8;
    const int akb = (lane >> 4) & 1;       // k-half (+8 halfs = 16B = 1 chunk)
    const int rB  = wn * 64 + lx + ((lane >> 4) & 1) * 8;
    const int bkb = (lane >> 3) & 1;
    const uint32_t aRow = (uint32_t)(rA * 128);
    const uint32_t bRow = 16384u + (uint32_t)(rB * 128);

    float acc[4][8][4];
    #pragma unroll
    for (int mi = 0; mi < 4; mi++)
        #pragma unroll
        for (int nj = 0; nj < 8; nj++)
            #pragma unroll
            for (int q = 0; q < 4; q++) acc[mi][nj][q] = 0.0f;

    load_stage(sbase, gA, gB, 0, tid);
    asm volatile("cp.async.commit_group;" ::: "memory");
    load_stage(sbase + STAGE_BYTES, gA, gB, 1, tid);
    asm volatile("cp.async.commit_group;" ::: "memory");

    #pragma unroll 1
    for (int it = 0; it < NIT; it++) {
        asm volatile("cp.async.wait_group 1;" ::: "memory");
        __syncthreads();
        int nx = it + STAGES - 1;
        if (nx < NIT)
            load_stage(sbase + (uint32_t)(nx % STAGES) * STAGE_BYTES, gA, gB, nx, tid);
        asm volatile("cp.async.commit_group;" ::: "memory");

        const uint32_t sm = sbase + (uint32_t)(it % STAGES) * STAGE_BYTES;
        #pragma unroll
        for (int ks = 0; ks < 4; ks++) {   // 4 x k16 per BK=64 stage
            const uint32_t cA = (uint32_t)(((ks * 2 + akb) ^ lx) << 4);
            const uint32_t cB = (uint32_t)(((ks * 2 + bkb) ^ lx) << 4);
            uint32_t a[4][4], b[4][4];
            #pragma unroll
            for (int mi = 0; mi < 4; mi++)
                ldsm4(a[mi], sm + aRow + (uint32_t)(mi * 2048) + cA);   // 16 rows = 2KB
            #pragma unroll
            for (int nj2 = 0; nj2 < 4; nj2++)
                ldsm4(b[nj2], sm + bRow + (uint32_t)(nj2 * 2048) + cB);
            #pragma unroll
            for (int mi = 0; mi < 4; mi++)
                #pragma unroll
                for (int nj2 = 0; nj2 < 4; nj2++) {
                    mma16(acc[mi][2 * nj2],     a[mi], b[nj2][0], b[nj2][1]);
                    mma16(acc[mi][2 * nj2 + 1], a[mi], b[nj2][2], b[nj2][3]);
                }
        }
    }

    const int qc   = lane & 3;
    const int rofs = lane >> 2;
    #pragma unroll
    for (int mi = 0; mi < 4; mi++) {
        const int row0 = M0 + wm * 64 + mi * 16 + rofs;
        #pragma unroll
        for (int nj = 0; nj < 8; nj++) {
            const int col = N0 + wn * 64 + nj * 8 + 2 * qc;
            *reinterpret_cast<float2*>(gP + (size_t)row0 * NC + col) =
                make_float2(acc[mi][nj][0], acc[mi][nj][1]);
            *reinterpret_cast<float2*>(gP + (size_t)(row0 + 8) * NC + col) =
                make_float2(acc[mi][nj][2], acc[mi][nj][3]);
        }
    }
}

// ================= Gauss combine + inverse transform + normalize =================
__global__ __launch_bounds__(256) void inv_norm(float* __restrict__ out) {
    int idx = blockIdx.x * 256 + threadIdx.x;     // (n,o), o fastest
    int n = idx >> 8, o = idx & 255;
    float Mre[4][4], Mim[4][4];
    #pragma unroll
    for (int c = 0; c < 4; c++) {
        size_t off = (size_t)(n * 4 + c) * NC + o * 4;
        float4 p1 = *reinterpret_cast<const float4*>(g_P + off);
        float4 p2 = *reinterpret_cast<const float4*>(g_P + P_CHUNK + off);
        float4 p3 = *reinterpret_cast<const float4*>(g_P + 2 * P_CHUNK + off);
        Mre[0][c] = p1.x - p2.x; Mim[0][c] = p3.x - p1.x - p2.x;
        Mre[1][c] = p1.y - p2.y; Mim[1][c] = p3.y - p1.y - p2.y;
        Mre[2][c] = p1.z - p2.z; Mim[2][c] = p3.z - p1.z - p2.z;
        Mre[3][c] = p1.w - p2.w; Mim[3][c] = p3.w - p1.w - p2.w;
    }
    float v[32];
    blades(v, Mre, Mim, std::make_integer_sequence<int, 32>{});
    float ss = 1e-6f;
    #pragma unroll
    for (int k = 0; k < 32; k++) ss += v[k] * v[k];
    float inv = rsqrtf(ss);
    float4* dst = reinterpret_cast<float4*>(out + (size_t)idx * 32);
    #pragma unroll
    for (int q = 0; q < 8; q++)
        dst[q] = make_float4(v[4*q] * inv, v[4*q+1] * inv, v[4*q+2] * inv, v[4*q+3] * inv);
}

// ================= host =================
extern "C" void kernel_launch(void* const* d_in, const int* in_sizes, int n_in,
                              void* d_out, int out_size) {
    const float* x = (const float*)d_in[0];   // [2048, 256, 32]
    const float* w = (const float*)d_in[1];   // [256, 256, 32]
    float* out = (float*)d_out;               // [2048, 256, 32]

    fwd_x<<<(NTOK * IFEAT) / 128, 128>>>(x);
    fwd_w<<<(OFEAT * IFEAT) / 128, 128>>>(w);

    cudaFuncSetAttribute(versor_mma, cudaFuncAttributeMaxDynamicSharedMemorySize, SMEM_TOTAL);
    dim3 grid(NC / BN, MDIM / BM, 3);
    versor_mma<<<grid, 128, SMEM_TOTAL>>>();

    inv_norm<<<(NTOK * OFEAT) / 256, 256>>>(out);
}